// round 10
// baseline (speedup 1.0000x reference)
#include <cuda_runtime.h>
#include <cuda_bf16.h>
#include <cstdint>
#include <math.h>

#define TSTEPS 512
#define BATCH  64
#define NIN    512
#define NH     1024
#define NBLK   128
#define NTHB   256

// ============================ global scratch ================================
__device__ float g_X[(size_t)3 * TSTEPS * BATCH * NH];   // input projections
__device__ float g_h32[BATCH * NH];                      // h (fp32, plain)
// A-operand planes in mma fragment order: frag(kf,mf)=kf*4+mf -> uint4[frag*32+lane]
__device__ uint4 g_hhf[2][8192], g_hlf[2][8192];         // h split planes (parity)
__device__ uint4 g_rhhf[8192], g_rhlf[8192];             // r*h split planes
__device__ float g_rpart[64 * 1024];                     // r high-K partials (zc->rc)
__device__ float g_zcpart[64 * 2048];                    // z-low | c-low partials (rc->zc)
__device__ int g_fh[64], g_frp[64], g_frh[64], g_fcp[64];

// ============================ helpers =======================================
__device__ __forceinline__ uint32_t bfpack(float x, float y) {
    __nv_bfloat162 t = __floats2bfloat162_rn(x, y);
    return *(uint32_t*)&t;
}
__device__ __forceinline__ void splitp(float x, float y, uint32_t& hi, uint32_t& lo) {
    float hx = __bfloat162float(__float2bfloat16(x));
    float hy = __bfloat162float(__float2bfloat16(y));
    hi = bfpack(hx, hy);
    lo = bfpack(x - hx, y - hy);
}
__device__ __forceinline__ void mma16816(float* c, const uint32_t* a, const uint32_t* b) {
    asm volatile("mma.sync.aligned.m16n8k16.row.col.f32.bf16.bf16.f32 "
        "{%0,%1,%2,%3},{%4,%5,%6,%7},{%8,%9},{%0,%1,%2,%3};"
        : "+f"(c[0]), "+f"(c[1]), "+f"(c[2]), "+f"(c[3])
        : "r"(a[0]), "r"(a[1]), "r"(a[2]), "r"(a[3]), "r"(b[0]), "r"(b[1]));
}
__device__ __forceinline__ int ld_acq(const int* p) {
    int v;
    asm volatile("ld.acquire.gpu.global.s32 %0, [%1];" : "=r"(v) : "l"(p) : "memory");
    return v;
}
__device__ __forceinline__ void st_rel(int* p, int v) {
    asm volatile("st.release.gpu.global.s32 [%0], %1;" :: "l"(p), "r"(v) : "memory");
}
// single-warp polling (warp 0), block released by syncthreads
__device__ __forceinline__ void block_wait64(const int* flags, int target) {
    if (threadIdx.x < 32) {
        const int* p0 = flags + threadIdx.x;
        const int* p1 = flags + 32 + threadIdx.x;
        while (!__all_sync(0xFFFFFFFFu,
                           (ld_acq(p0) >= target) && (ld_acq(p1) >= target)))
            __nanosleep(60);
    }
    __syncthreads();
}
__device__ __forceinline__ void block_wait32(const int* flags, int target) {
    if (threadIdx.x < 32) {
        while (!__all_sync(0xFFFFFFFFu, ld_acq(flags + threadIdx.x) >= target))
            __nanosleep(60);
    }
    __syncthreads();
}
__device__ __forceinline__ void block_wait1(const int* flag, int target) {
    if (threadIdx.x == 0) {
        while (ld_acq(flag) < target) __nanosleep(60);
    }
    __syncthreads();
}

// =================== init: reset flags each launch ==========================
__global__ void init_misc_kernel() {
    int i = threadIdx.x;
    if (i < 64) { g_fh[i] = -1; g_frp[i] = -1; g_frh[i] = -1; g_fcp[i] = -1; }
}

// ======================= phase A: input projections =========================
#define PA_AH 0
#define PA_AL 32768
#define PA_WH 65536
#define PA_WL 98304
#define PA_SMEM 131072

__global__ void __launch_bounds__(256) input_proj_kernel(
    const float* __restrict__ input,
    const float* __restrict__ Wiz, const float* __restrict__ Wir,
    const float* __restrict__ Wih)
{
    extern __shared__ char sm[];
    uint4* Ah = (uint4*)(sm + PA_AH);
    uint4* Al = (uint4*)(sm + PA_AL);
    uint2* Wh = (uint2*)(sm + PA_WH);
    uint2* Wl = (uint2*)(sm + PA_WL);
    const int tid = threadIdx.x, wid = tid >> 5, lane = tid & 31;
    const int ntile = blockIdx.x % 24, mtile = blockIdx.x / 24;
    const int gate = ntile >> 3, n0g = (ntile & 7) * 128, m0 = mtile * 128;
    const float* W = (gate == 0) ? Wiz : ((gate == 1) ? Wir : Wih);
    const int mg = wid & 3, ng = wid >> 2;

    float c[2][8][4];
#pragma unroll
    for (int i = 0; i < 2; i++)
#pragma unroll
        for (int j = 0; j < 8; j++)
#pragma unroll
            for (int k = 0; k < 4; k++) c[i][j][k] = 0.0f;

    for (int ch = 0; ch < 4; ch++) {
        const int k0 = ch * 128;
        __syncthreads();
#pragma unroll
        for (int it = 0; it < 8; it++) {
            int idx = tid + (it << 8);
            int frag = idx >> 5, l = idx & 31;
            int kf = frag >> 3, mf = frag & 7;
            int r = l >> 2, c2 = (l & 3) * 2;
            const float* src = input + (size_t)(m0 + mf * 16 + r) * NIN + k0 + kf * 16 + c2;
            float2 p0 = *(const float2*)(src);
            float2 p1 = *(const float2*)(src + 8 * NIN);
            float2 p2 = *(const float2*)(src + 8);
            float2 p3 = *(const float2*)(src + 8 * NIN + 8);
            uint32_t h0, h1, h2, h3, lo0, lo1, lo2, lo3;
            splitp(p0.x, p0.y, h0, lo0); splitp(p1.x, p1.y, h1, lo1);
            splitp(p2.x, p2.y, h2, lo2); splitp(p3.x, p3.y, h3, lo3);
            Ah[frag * 32 + l] = make_uint4(h0, h1, h2, h3);
            Al[frag * 32 + l] = make_uint4(lo0, lo1, lo2, lo3);
        }
#pragma unroll
        for (int it = 0; it < 16; it++) {
            int idx = tid + (it << 8);
            int frag = idx >> 5, l = idx & 31;
            int kf = frag >> 4, nf = frag & 15;
            int n = nf * 8 + (l >> 2), k = kf * 16 + (l & 3) * 2;
            const float* src = W + (size_t)(n0g + n) * NIN + k0 + k;
            float2 q0 = *(const float2*)src;
            float2 q1 = *(const float2*)(src + 8);
            uint32_t h0, h1, lo0, lo1;
            splitp(q0.x, q0.y, h0, lo0); splitp(q1.x, q1.y, h1, lo1);
            Wh[frag * 32 + l] = make_uint2(h0, h1);
            Wl[frag * 32 + l] = make_uint2(lo0, lo1);
        }
        __syncthreads();
#pragma unroll 2
        for (int s = 0; s < 8; s++) {
            uint4 ah[2], al[2];
            uint2 bh[8], bl[8];
            ah[0] = Ah[(s * 8 + mg * 2 + 0) * 32 + lane];
            ah[1] = Ah[(s * 8 + mg * 2 + 1) * 32 + lane];
            al[0] = Al[(s * 8 + mg * 2 + 0) * 32 + lane];
            al[1] = Al[(s * 8 + mg * 2 + 1) * 32 + lane];
#pragma unroll
            for (int nf = 0; nf < 8; nf++) {
                bh[nf] = Wh[(s * 16 + ng * 8 + nf) * 32 + lane];
                bl[nf] = Wl[(s * 16 + ng * 8 + nf) * 32 + lane];
            }
#pragma unroll
            for (int mf = 0; mf < 2; mf++)
#pragma unroll
                for (int nf = 0; nf < 8; nf++) {
                    mma16816(c[mf][nf], &ah[mf].x, &bh[nf].x);
                    mma16816(c[mf][nf], &al[mf].x, &bh[nf].x);
                    mma16816(c[mf][nf], &ah[mf].x, &bl[nf].x);
                }
        }
    }
    const int r = lane >> 2, c2 = (lane & 3) * 2;
#pragma unroll
    for (int mf = 0; mf < 2; mf++)
#pragma unroll
        for (int nf = 0; nf < 8; nf++) {
            size_t row = (size_t)(m0 + (mg * 2 + mf) * 16 + r);
            size_t base = ((size_t)gate * TSTEPS * BATCH + row) * NH
                        + n0g + (ng * 8 + nf) * 8 + c2;
            *(float2*)(g_X + base) = make_float2(c[mf][nf][0], c[mf][nf][1]);
            *(float2*)(g_X + base + (size_t)8 * NH) = make_float2(c[mf][nf][2], c[mf][nf][3]);
        }
}

// ======================= phase B: persistent GRU ============================
// 64 pairs x 16 cols. zc (b<64): K-high halves of {z,r fused; c} + final update.
// rc (b>=64): K-low halves of {z,r fused; c} + r merge + rh pack.
#define W_ZH 0          // z-half W hi: 64 frags x 32 x 8B = 16KB
#define W_ZL 16384
#define W_RH 32768
#define W_RL 49152
#define W_CH 65536
#define W_CL 81920
#define PB_SCRZ 98304   // float[4][64][20] = 20480 (also c-gemm scr)
#define PB_SCRR 118784  // float[4][64][20] = 20480
#define PB_SBUF 139264  // float[64][20]    =  5120
#define PB_BIA  144384  // float[32]
#define PB_SLEN 144512  // int[64]
#define PB_SMEM 144768

// pack one K-half (16 cols x 512 K) of W into 64 B-frag-order split frags
__device__ __forceinline__ void packW(const float* __restrict__ W, int gn0, int koff,
                                      uint2* __restrict__ Dh, uint2* __restrict__ Dl,
                                      int tid)
{
#pragma unroll 4
    for (int it = 0; it < 8; it++) {
        int idx = tid + (it << 8);
        int frag = idx >> 5, l = idx & 31;
        int lf = frag >> 1, nf = frag & 1;
        int n = nf * 8 + (l >> 2), k = koff + lf * 16 + (l & 3) * 2;
        const float* src = W + (size_t)(gn0 + n) * NH + k;
        float2 q0 = *(const float2*)src;
        float2 q1 = *(const float2*)(src + 8);
        uint32_t h0, h1, lo0, lo1;
        splitp(q0.x, q0.y, h0, lo0); splitp(q1.x, q1.y, h1, lo1);
        Dh[frag * 32 + l] = make_uint2(h0, h1);
        Dl[frag * 32 + l] = make_uint2(lo0, lo1);
    }
}

// fused 2-gate K-half gemm: reads A once, accumulates z and r partials.
// 8 warps: mg=wid&1 (32 rows), kg=wid>>1 (4 groups x 8 kf). 3-term split.
__device__ __forceinline__ void gemm_fused(const uint4* __restrict__ Aph,
                                           const uint4* __restrict__ Apl,
                                           int akf0,
                                           const uint2* __restrict__ Wzh, const uint2* __restrict__ Wzl,
                                           const uint2* __restrict__ Wrh, const uint2* __restrict__ Wrl,
                                           float* __restrict__ scrz, float* __restrict__ scrr,
                                           int wid, int lane)
{
    const int mg = wid & 1, kg = wid >> 1;
    float cz[2][2][4], cr[2][2][4];
#pragma unroll
    for (int i = 0; i < 2; i++)
#pragma unroll
        for (int j = 0; j < 2; j++)
#pragma unroll
            for (int k = 0; k < 4; k++) { cz[i][j][k] = 0.0f; cr[i][j][k] = 0.0f; }

    uint4 ah[2][2], al[2][2];
    {
        int af = ((akf0 + kg * 8) * 4 + mg * 2) * 32 + lane;
        ah[0][0] = Aph[af]; ah[0][1] = Aph[af + 32];
        al[0][0] = Apl[af]; al[0][1] = Apl[af + 32];
    }
#pragma unroll
    for (int s = 0; s < 8; s++) {
        const int cur = s & 1, nxt = cur ^ 1;
        if (s < 7) {
            int af = ((akf0 + kg * 8 + s + 1) * 4 + mg * 2) * 32 + lane;
            ah[nxt][0] = Aph[af]; ah[nxt][1] = Aph[af + 32];
            al[nxt][0] = Apl[af]; al[nxt][1] = Apl[af + 32];
        }
        int wf = ((kg * 8 + s) * 2) * 32 + lane;
        uint2 bzh[2] = {Wzh[wf], Wzh[wf + 32]};
        uint2 bzl[2] = {Wzl[wf], Wzl[wf + 32]};
        uint2 brh[2] = {Wrh[wf], Wrh[wf + 32]};
        uint2 brl[2] = {Wrl[wf], Wrl[wf + 32]};
#pragma unroll
        for (int mf = 0; mf < 2; mf++)
#pragma unroll
            for (int nf = 0; nf < 2; nf++) {
                mma16816(cz[mf][nf], &ah[cur][mf].x, &bzh[nf].x);
                mma16816(cz[mf][nf], &al[cur][mf].x, &bzh[nf].x);
                mma16816(cz[mf][nf], &ah[cur][mf].x, &bzl[nf].x);
                mma16816(cr[mf][nf], &ah[cur][mf].x, &brh[nf].x);
                mma16816(cr[mf][nf], &al[cur][mf].x, &brh[nf].x);
                mma16816(cr[mf][nf], &ah[cur][mf].x, &brl[nf].x);
            }
    }
    const int r = lane >> 2, c2 = (lane & 3) * 2;
#pragma unroll
    for (int mf = 0; mf < 2; mf++)
#pragma unroll
        for (int nf = 0; nf < 2; nf++) {
            int off = (kg * 64 + mg * 32 + mf * 16 + r) * 20 + nf * 8 + c2;
            *(float2*)(scrz + off) = make_float2(cz[mf][nf][0], cz[mf][nf][1]);
            *(float2*)(scrz + off + 8 * 20) = make_float2(cz[mf][nf][2], cz[mf][nf][3]);
            *(float2*)(scrr + off) = make_float2(cr[mf][nf][0], cr[mf][nf][1]);
            *(float2*)(scrr + off + 8 * 20) = make_float2(cr[mf][nf][2], cr[mf][nf][3]);
        }
}

// single-gate K-half gemm (candidate halves), KF=8 per warp
__device__ __forceinline__ void gemm_c(const uint4* __restrict__ Aph,
                                       const uint4* __restrict__ Apl,
                                       int akf0,
                                       const uint2* __restrict__ Wh,
                                       const uint2* __restrict__ Wl,
                                       float* __restrict__ scr,
                                       int wid, int lane)
{
    const int mg = wid & 1, kg = wid >> 1;
    float c[2][2][4];
#pragma unroll
    for (int i = 0; i < 2; i++)
#pragma unroll
        for (int j = 0; j < 2; j++)
#pragma unroll
            for (int k = 0; k < 4; k++) c[i][j][k] = 0.0f;

    uint4 ah[2][2], al[2][2];
    uint2 bh[2][2], bl[2][2];
    {
        int af = ((akf0 + kg * 8) * 4 + mg * 2) * 32 + lane;
        ah[0][0] = Aph[af]; ah[0][1] = Aph[af + 32];
        al[0][0] = Apl[af]; al[0][1] = Apl[af + 32];
        int wf = (kg * 8 * 2) * 32 + lane;
        bh[0][0] = Wh[wf]; bh[0][1] = Wh[wf + 32];
        bl[0][0] = Wl[wf]; bl[0][1] = Wl[wf + 32];
    }
#pragma unroll
    for (int s = 0; s < 8; s++) {
        const int cur = s & 1, nxt = cur ^ 1;
        if (s < 7) {
            int af = ((akf0 + kg * 8 + s + 1) * 4 + mg * 2) * 32 + lane;
            ah[nxt][0] = Aph[af]; ah[nxt][1] = Aph[af + 32];
            al[nxt][0] = Apl[af]; al[nxt][1] = Apl[af + 32];
            int wf = ((kg * 8 + s + 1) * 2) * 32 + lane;
            bh[nxt][0] = Wh[wf]; bh[nxt][1] = Wh[wf + 32];
            bl[nxt][0] = Wl[wf]; bl[nxt][1] = Wl[wf + 32];
        }
#pragma unroll
        for (int mf = 0; mf < 2; mf++)
#pragma unroll
            for (int nf = 0; nf < 2; nf++) {
                mma16816(c[mf][nf], &ah[cur][mf].x, &bh[cur][nf].x);
                mma16816(c[mf][nf], &al[cur][mf].x, &bh[cur][nf].x);
                mma16816(c[mf][nf], &ah[cur][mf].x, &bl[cur][nf].x);
            }
    }
    const int r = lane >> 2, c2 = (lane & 3) * 2;
#pragma unroll
    for (int mf = 0; mf < 2; mf++)
#pragma unroll
        for (int nf = 0; nf < 2; nf++) {
            int off = (kg * 64 + mg * 32 + mf * 16 + r) * 20 + nf * 8 + c2;
            *(float2*)(scr + off) = make_float2(c[mf][nf][0], c[mf][nf][1]);
            *(float2*)(scr + off + 8 * 20) = make_float2(c[mf][nf][2], c[mf][nf][3]);
        }
}

__device__ __forceinline__ void reduce4(const float* __restrict__ scr,
                                        int m, int nq, float* pre)
{
#pragma unroll
    for (int kg = 0; kg < 4; kg++) {
        float4 a = *(const float4*)(scr + kg * 1280 + m * 20 + nq);
        pre[0] += a.x; pre[1] += a.y; pre[2] += a.z; pre[3] += a.w;
    }
}

// pack sbuf[64][20] (16 cols of values) into A-frag planes at kf = jkf
__device__ __forceinline__ void pack16(const float* __restrict__ sbuf,
                                       uint4* __restrict__ dsth,
                                       uint4* __restrict__ dstl,
                                       int jkf, int wid, int lane)
{
    if (wid < 4) {
        const int mf = wid;
        const int r = lane >> 2, c2 = (lane & 3) * 2;
        const float* p = sbuf + (mf * 16 + r) * 20 + c2;
        uint32_t h0, h1, h2, h3, l0, l1, l2, l3;
        splitp(p[0], p[1], h0, l0);
        splitp(p[160], p[161], h1, l1);
        splitp(p[8], p[9], h2, l2);
        splitp(p[168], p[169], h3, l3);
        const int fi = (jkf * 4 + mf) * 32 + lane;
        dsth[fi] = make_uint4(h0, h1, h2, h3);
        dstl[fi] = make_uint4(l0, l1, l2, l3);
    }
}

__global__ void __launch_bounds__(NTHB, 1) gru_step_kernel(
    const float* __restrict__ h0in,
    const float* __restrict__ Whz, const float* __restrict__ Whr,
    const float* __restrict__ Whh,
    const float* __restrict__ Whz_b, const float* __restrict__ Whr_b,
    const float* __restrict__ Whh_b,
    const float* __restrict__ Wiz_b, const float* __restrict__ Wir_b,
    const float* __restrict__ Wih_b,
    const void* __restrict__ lengths,
    float* __restrict__ out, int write_last)
{
    extern __shared__ char sm[];
    uint2* Wzh = (uint2*)(sm + W_ZH);
    uint2* Wzl = (uint2*)(sm + W_ZL);
    uint2* Wrh = (uint2*)(sm + W_RH);
    uint2* Wrl = (uint2*)(sm + W_RL);
    uint2* Wch = (uint2*)(sm + W_CH);
    uint2* Wcl = (uint2*)(sm + W_CL);
    float* scrz = (float*)(sm + PB_SCRZ);
    float* scrr = (float*)(sm + PB_SCRR);
    float* sbuf = (float*)(sm + PB_SBUF);
    float* bia = (float*)(sm + PB_BIA);     // [0:16) own gate, [16:32) cand (zc)
    int* slen = (int*)(sm + PB_SLEN);

    const int tid = threadIdx.x, wid = tid >> 5, lane = tid & 31;
    const int b = blockIdx.x;
    const int is_zc = (b < 64);
    const int j = b & 63;
    const int gn0 = j * 16;
    const int koff = is_zc ? 512 : 0;
    const int akf0 = is_zc ? 32 : 0;

    // pack W K-halves: z, r, c  (each 16 cols x 512 K)
    packW(Whz, gn0, koff, Wzh, Wzl, tid);
    packW(Whr, gn0, koff, Wrh, Wrl, tid);
    packW(Whh, gn0, koff, Wch, Wcl, tid);
    if (tid < 16) {
        bia[tid] = is_zc ? (Whz_b[gn0 + tid] + Wiz_b[gn0 + tid])
                         : (Whr_b[gn0 + tid] + Wir_b[gn0 + tid]);
        bia[16 + tid] = Whh_b[gn0 + tid] + Wih_b[gn0 + tid];
    }
    {   // lengths dtype auto-detect (int64 -> high word of elem0 is 0)
        const int* L32 = (const int*)lengths;
        int is64 = (L32[1] == 0);
        if (tid < BATCH)
            slen[tid] = is64 ? (int)((const long long*)lengths)[tid] : L32[tid];
    }

    const int m = tid >> 2, nq = (tid & 3) * 4;
    float hreg[4];

    if (is_zc) {
        const float* src = h0in + (size_t)m * NH + gn0 + nq;
        float4 v = *(const float4*)src;
        hreg[0] = v.x; hreg[1] = v.y; hreg[2] = v.z; hreg[3] = v.w;
        *(float4*)(g_h32 + (size_t)m * NH + gn0 + nq) = v;
        *(float4*)(sbuf + m * 20 + nq) = v;
        __syncthreads();
        pack16(sbuf, g_hhf[0], g_hlf[0], j, wid, lane);
        __syncthreads();
        if (tid == 0) { __threadfence(); st_rel(&g_fh[j], 0); }
    } else {
        __syncthreads();
    }

    const int sl = slen[m];
    const size_t GATE = (size_t)TSTEPS * BATCH * NH;
    const size_t xrow = (size_t)m * NH + gn0 + nq;

    if (is_zc) {
        const float* Xz = g_X + xrow;               // gate 0
        const float* Xh = g_X + 2 * GATE + xrow;    // gate 2
        float* rp = g_rpart + j * 1024 + m * 16 + nq;
        const float* zcp = g_zcpart + j * 2048 + m * 16 + nq;
        for (int t = 0; t < TSTEPS; t++) {
            float4 xz = *(const float4*)(Xz + (size_t)t * BATCH * NH);
            float4 xh = *(const float4*)(Xh + (size_t)t * BATCH * NH);
            block_wait64(g_fh, t);
            gemm_fused(g_hhf[t & 1], g_hlf[t & 1], akf0, Wzh, Wzl, Wrh, Wrl,
                       scrz, scrr, wid, lane);
            __syncthreads();
            float zacc[4] = {0.0f, 0.0f, 0.0f, 0.0f};
            reduce4(scrz, m, nq, zacc);
            float racc[4] = {0.0f, 0.0f, 0.0f, 0.0f};
            reduce4(scrr, m, nq, racc);
            *(float4*)rp = make_float4(racc[0], racc[1], racc[2], racc[3]);
            __syncthreads();
            if (tid == 0) { __threadfence(); st_rel(&g_frp[j], t + 1); }
            // ---- c high-K half on rh planes (kf 32..63) ----
            block_wait32(g_frh + 32, t + 1);
            gemm_c(g_rhhf, g_rhlf, 32, Wch, Wcl, scrz, wid, lane);
            __syncthreads();
            block_wait1(&g_fcp[j], t + 1);
            float4 zl = *(const float4*)zcp;
            float4 cp = *(const float4*)(zcp + 1024);
            float zv[4] = {zacc[0] + zl.x + bia[nq] + xz.x,
                           zacc[1] + zl.y + bia[nq + 1] + xz.y,
                           zacc[2] + zl.z + bia[nq + 2] + xz.z,
                           zacc[3] + zl.w + bia[nq + 3] + xz.w};
#pragma unroll
            for (int jj = 0; jj < 4; jj++) zv[jj] = 1.0f / (1.0f + expf(-zv[jj]));
            float pre[4] = {xh.x + bia[16 + nq] + cp.x, xh.y + bia[16 + nq + 1] + cp.y,
                            xh.z + bia[16 + nq + 2] + cp.z, xh.w + bia[16 + nq + 3] + cp.w};
            reduce4(scrz, m, nq, pre);
            float hn[4];
#pragma unroll
            for (int jj = 0; jj < 4; jj++) {
                float hc = tanhf(pre[jj]);
                float v = (1.0f - zv[jj]) * hreg[jj] + zv[jj] * hc;
                if (t >= sl) v = hreg[jj];
                hreg[jj] = v;
                hn[jj] = v;
            }
            float4 hv = make_float4(hn[0], hn[1], hn[2], hn[3]);
            *(float4*)(g_h32 + (size_t)m * NH + gn0 + nq) = hv;
            *(float4*)(out + (size_t)t * BATCH * NH + xrow) = hv;
            *(float4*)(sbuf + m * 20 + nq) = hv;
            __syncthreads();
            pack16(sbuf, g_hhf[(t + 1) & 1], g_hlf[(t + 1) & 1], j, wid, lane);
            __syncthreads();
            if (tid == 0) { __threadfence(); st_rel(&g_fh[j], t + 1); }
        }
        if (write_last) {
            *(float4*)(out + (size_t)TSTEPS * BATCH * NH + xrow) =
                make_float4(hreg[0], hreg[1], hreg[2], hreg[3]);
        }
    } else {
        const float* Xr = g_X + GATE + xrow;        // gate 1
        const float* rp = g_rpart + j * 1024 + m * 16 + nq;
        float* zcp = g_zcpart + j * 2048 + m * 16 + nq;
        for (int t = 0; t < TSTEPS; t++) {
            float4 xr = *(const float4*)(Xr + (size_t)t * BATCH * NH);
            block_wait64(g_fh, t);
            gemm_fused(g_hhf[t & 1], g_hlf[t & 1], akf0, Wzh, Wzl, Wrh, Wrl,
                       scrz, scrr, wid, lane);
            __syncthreads();
            float zlo[4] = {0.0f, 0.0f, 0.0f, 0.0f};
            reduce4(scrz, m, nq, zlo);
            float rlo[4] = {0.0f, 0.0f, 0.0f, 0.0f};
            reduce4(scrr, m, nq, rlo);
            // ---- merge r with zc's high partial, build rh ----
            block_wait1(&g_frp[j], t + 1);
            float4 rhi = *(const float4*)rp;
            float4 hp = *(const float4*)(g_h32 + (size_t)m * NH + gn0 + nq);
            float hvv[4] = {hp.x, hp.y, hp.z, hp.w};
            float rhiv[4] = {rhi.x, rhi.y, rhi.z, rhi.w};
            float rh[4];
#pragma unroll
            for (int jj = 0; jj < 4; jj++) {
                float s = 1.0f / (1.0f + expf(-(rlo[jj] + rhiv[jj] + bia[nq + jj] + ((const float*)&xr)[jj])));
                rh[jj] = s * hvv[jj];
            }
            *(float4*)(sbuf + m * 20 + nq) = make_float4(rh[0], rh[1], rh[2], rh[3]);
            __syncthreads();
            pack16(sbuf, g_rhhf, g_rhlf, j, wid, lane);
            __syncthreads();
            if (tid == 0) { __threadfence(); st_rel(&g_frh[j], t + 1); }
            // ---- c low-K half on rh planes (kf 0..31) ----
            block_wait32(g_frh, t + 1);
            gemm_c(g_rhhf, g_rhlf, 0, Wch, Wcl, scrz, wid, lane);
            __syncthreads();
            float clo[4] = {0.0f, 0.0f, 0.0f, 0.0f};
            reduce4(scrz, m, nq, clo);
            *(float4*)zcp = make_float4(zlo[0], zlo[1], zlo[2], zlo[3]);
            *(float4*)(zcp + 1024) = make_float4(clo[0], clo[1], clo[2], clo[3]);
            __syncthreads();
            if (tid == 0) { __threadfence(); st_rel(&g_fcp[j], t + 1); }
        }
    }
}

// ============================= launch =======================================
extern "C" void kernel_launch(void* const* d_in, const int* in_sizes, int n_in,
                              void* d_out, int out_size)
{
    const float* input = (const float*)d_in[0];
    const float* h0    = (const float*)d_in[1];
    const float* Wiz_w = (const float*)d_in[2];
    const float* Wiz_b = (const float*)d_in[3];
    const float* Wir_w = (const float*)d_in[4];
    const float* Wir_b = (const float*)d_in[5];
    const float* Wih_w = (const float*)d_in[6];
    const float* Wih_b = (const float*)d_in[7];
    const float* Whz_w = (const float*)d_in[8];
    const float* Whz_b = (const float*)d_in[9];
    const float* Whr_w = (const float*)d_in[10];
    const float* Whr_b = (const float*)d_in[11];
    const float* Whh_w = (const float*)d_in[12];
    const float* Whh_b = (const float*)d_in[13];
    const void*  lengths = d_in[14];

    cudaFuncSetAttribute(input_proj_kernel,
                         cudaFuncAttributeMaxDynamicSharedMemorySize, PA_SMEM);
    cudaFuncSetAttribute(gru_step_kernel,
                         cudaFuncAttributeMaxDynamicSharedMemorySize, PB_SMEM);

    init_misc_kernel<<<1, 64>>>();
    input_proj_kernel<<<256 * 24, 256, PA_SMEM>>>(input, Wiz_w, Wir_w, Wih_w);

    int write_last = (out_size >= TSTEPS * BATCH * NH + BATCH * NH) ? 1 : 0;
    gru_step_kernel<<<NBLK, NTHB, PB_SMEM>>>(
        h0, Whz_w, Whr_w, Whh_w, Whz_b, Whr_b, Whh_b,
        Wiz_b, Wir_b, Wih_b, lengths, (float*)d_out, write_last);
}

// round 11
// speedup vs baseline: 1.1055x; 1.1055x over previous
#include <cuda_runtime.h>
#include <cuda_bf16.h>
#include <cstdint>
#include <math.h>

#define TSTEPS 512
#define BATCH  64
#define NIN    512
#define NH     1024
#define NBLK   128

// ============================ global scratch ================================
__device__ float g_X[(size_t)3 * TSTEPS * BATCH * NH];   // input projections
__device__ float g_h32[BATCH * NH];                      // h (fp32, plain)
// A-operand planes in mma fragment order: frag(kf,mf)=kf*4+mf -> uint4[frag*32+lane]
__device__ uint4 g_hhf[2][8192], g_hlf[2][8192];         // h split planes (parity)
__device__ uint4 g_rhhf[8192], g_rhlf[8192];             // r*h split planes
__device__ float g_cpart[64 * 64 * 16];                  // c-gemm low-K partials
__device__ int g_fh[64], g_frh[64], g_fcp[64];           // step flags

// ============================ helpers =======================================
__device__ __forceinline__ uint32_t bfpack(float x, float y) {
    __nv_bfloat162 t = __floats2bfloat162_rn(x, y);
    return *(uint32_t*)&t;
}
__device__ __forceinline__ void splitp(float x, float y, uint32_t& hi, uint32_t& lo) {
    float hx = __bfloat162float(__float2bfloat16(x));
    float hy = __bfloat162float(__float2bfloat16(y));
    hi = bfpack(hx, hy);
    lo = bfpack(x - hx, y - hy);
}
__device__ __forceinline__ void mma16816(float* c, const uint32_t* a, const uint32_t* b) {
    asm volatile("mma.sync.aligned.m16n8k16.row.col.f32.bf16.bf16.f32 "
        "{%0,%1,%2,%3},{%4,%5,%6,%7},{%8,%9},{%0,%1,%2,%3};"
        : "+f"(c[0]), "+f"(c[1]), "+f"(c[2]), "+f"(c[3])
        : "r"(a[0]), "r"(a[1]), "r"(a[2]), "r"(a[3]), "r"(b[0]), "r"(b[1]));
}
__device__ __forceinline__ int ld_acq(const int* p) {
    int v;
    asm volatile("ld.acquire.gpu.global.s32 %0, [%1];" : "=r"(v) : "l"(p) : "memory");
    return v;
}
// release store: bar.sync (CTA-scope fence) before this + st.release.gpu gives
// cumulative ordering for all block threads' prior writes. No membar.gl needed.
__device__ __forceinline__ void st_rel(int* p, int v) {
    asm volatile("st.release.gpu.global.s32 [%0], %1;" :: "l"(p), "r"(v) : "memory");
}
// single-warp polling (warp 0), block released by syncthreads
__device__ __forceinline__ void block_wait64(const int* flags, int target) {
    if (threadIdx.x < 32) {
        const int* p0 = flags + threadIdx.x;
        const int* p1 = flags + 32 + threadIdx.x;
        while (!__all_sync(0xFFFFFFFFu,
                           (ld_acq(p0) >= target) && (ld_acq(p1) >= target)))
            __nanosleep(40);
    }
    __syncthreads();
}
__device__ __forceinline__ void block_wait32(const int* flags, int target) {
    if (threadIdx.x < 32) {
        while (!__all_sync(0xFFFFFFFFu, ld_acq(flags + threadIdx.x) >= target))
            __nanosleep(40);
    }
    __syncthreads();
}
__device__ __forceinline__ void block_wait1(const int* flag, int target) {
    if (threadIdx.x == 0) {
        while (ld_acq(flag) < target) __nanosleep(40);
    }
    __syncthreads();
}

// =================== init: reset flags each launch ==========================
__global__ void init_misc_kernel() {
    int i = threadIdx.x;
    if (i < 64) { g_fh[i] = -1; g_frh[i] = -1; g_fcp[i] = -1; }
}

// ======================= phase A: input projections =========================
#define PA_AH 0
#define PA_AL 32768
#define PA_WH 65536
#define PA_WL 98304
#define PA_SMEM 131072

__global__ void __launch_bounds__(256) input_proj_kernel(
    const float* __restrict__ input,
    const float* __restrict__ Wiz, const float* __restrict__ Wir,
    const float* __restrict__ Wih)
{
    extern __shared__ char sm[];
    uint4* Ah = (uint4*)(sm + PA_AH);
    uint4* Al = (uint4*)(sm + PA_AL);
    uint2* Wh = (uint2*)(sm + PA_WH);
    uint2* Wl = (uint2*)(sm + PA_WL);
    const int tid = threadIdx.x, wid = tid >> 5, lane = tid & 31;
    const int ntile = blockIdx.x % 24, mtile = blockIdx.x / 24;
    const int gate = ntile >> 3, n0g = (ntile & 7) * 128, m0 = mtile * 128;
    const float* W = (gate == 0) ? Wiz : ((gate == 1) ? Wir : Wih);
    const int mg = wid & 3, ng = wid >> 2;

    float c[2][8][4];
#pragma unroll
    for (int i = 0; i < 2; i++)
#pragma unroll
        for (int j = 0; j < 8; j++)
#pragma unroll
            for (int k = 0; k < 4; k++) c[i][j][k] = 0.0f;

    for (int ch = 0; ch < 4; ch++) {
        const int k0 = ch * 128;
        __syncthreads();
#pragma unroll
        for (int it = 0; it < 8; it++) {
            int idx = tid + (it << 8);
            int frag = idx >> 5, l = idx & 31;
            int kf = frag >> 3, mf = frag & 7;
            int r = l >> 2, c2 = (l & 3) * 2;
            const float* src = input + (size_t)(m0 + mf * 16 + r) * NIN + k0 + kf * 16 + c2;
            float2 p0 = *(const float2*)(src);
            float2 p1 = *(const float2*)(src + 8 * NIN);
            float2 p2 = *(const float2*)(src + 8);
            float2 p3 = *(const float2*)(src + 8 * NIN + 8);
            uint32_t h0, h1, h2, h3, lo0, lo1, lo2, lo3;
            splitp(p0.x, p0.y, h0, lo0); splitp(p1.x, p1.y, h1, lo1);
            splitp(p2.x, p2.y, h2, lo2); splitp(p3.x, p3.y, h3, lo3);
            Ah[frag * 32 + l] = make_uint4(h0, h1, h2, h3);
            Al[frag * 32 + l] = make_uint4(lo0, lo1, lo2, lo3);
        }
#pragma unroll
        for (int it = 0; it < 16; it++) {
            int idx = tid + (it << 8);
            int frag = idx >> 5, l = idx & 31;
            int kf = frag >> 4, nf = frag & 15;
            int n = nf * 8 + (l >> 2), k = kf * 16 + (l & 3) * 2;
            const float* src = W + (size_t)(n0g + n) * NIN + k0 + k;
            float2 q0 = *(const float2*)src;
            float2 q1 = *(const float2*)(src + 8);
            uint32_t h0, h1, lo0, lo1;
            splitp(q0.x, q0.y, h0, lo0); splitp(q1.x, q1.y, h1, lo1);
            Wh[frag * 32 + l] = make_uint2(h0, h1);
            Wl[frag * 32 + l] = make_uint2(lo0, lo1);
        }
        __syncthreads();
#pragma unroll 2
        for (int s = 0; s < 8; s++) {
            uint4 ah[2], al[2];
            uint2 bh[8], bl[8];
            ah[0] = Ah[(s * 8 + mg * 2 + 0) * 32 + lane];
            ah[1] = Ah[(s * 8 + mg * 2 + 1) * 32 + lane];
            al[0] = Al[(s * 8 + mg * 2 + 0) * 32 + lane];
            al[1] = Al[(s * 8 + mg * 2 + 1) * 32 + lane];
#pragma unroll
            for (int nf = 0; nf < 8; nf++) {
                bh[nf] = Wh[(s * 16 + ng * 8 + nf) * 32 + lane];
                bl[nf] = Wl[(s * 16 + ng * 8 + nf) * 32 + lane];
            }
#pragma unroll
            for (int mf = 0; mf < 2; mf++)
#pragma unroll
                for (int nf = 0; nf < 8; nf++) {
                    mma16816(c[mf][nf], &ah[mf].x, &bh[nf].x);
                    mma16816(c[mf][nf], &al[mf].x, &bh[nf].x);
                    mma16816(c[mf][nf], &ah[mf].x, &bl[nf].x);
                }
        }
    }
    const int r = lane >> 2, c2 = (lane & 3) * 2;
#pragma unroll
    for (int mf = 0; mf < 2; mf++)
#pragma unroll
        for (int nf = 0; nf < 8; nf++) {
            size_t row = (size_t)(m0 + (mg * 2 + mf) * 16 + r);
            size_t base = ((size_t)gate * TSTEPS * BATCH + row) * NH
                        + n0g + (ng * 8 + nf) * 8 + c2;
            *(float2*)(g_X + base) = make_float2(c[mf][nf][0], c[mf][nf][1]);
            *(float2*)(g_X + base + (size_t)8 * NH) = make_float2(c[mf][nf][2], c[mf][nf][3]);
        }
}

// ======================= phase B: persistent GRU ============================
// 128 blocks. 0-63 "zc": z-gate (16 cols) + c high-K half + h update.
// 64-127 "rc": r-gate (16 cols) + c low-K half (partials to paired zc block).
#define W1_H 0          // gate W hi (128 frags)   32768
#define W1_L 32768
#define W2_H 65536      // c-half W hi (64 frags)  16384
#define W2_L 81920
#define PB_SCR  98304   // float[4][64][20]        20480
#define PB_SBUF 118784  // float[64][20]            5120
#define PB_BIA  123904  // float[32]  (biaG | biaC)
#define PB_SLEN 124032  // int[64]
#define PB_SMEM 124416

// C[64 x 16] += A[64 x 16*KF*4] @ W^T, 3-term, depth-2 operand pipeline.
template<int KF>
__device__ __forceinline__ void gemm_t(const uint4* __restrict__ Aph,
                                       const uint4* __restrict__ Apl,
                                       int akf0,
                                       const uint2* __restrict__ Wh,
                                       const uint2* __restrict__ Wl,
                                       float* __restrict__ scr,
                                       int wid, int lane)
{
    const int mg = wid & 1, kg = wid >> 1;
    const int kfl0 = kg * KF;
    float c[2][2][4];
#pragma unroll
    for (int i = 0; i < 2; i++)
#pragma unroll
        for (int j = 0; j < 2; j++)
#pragma unroll
            for (int k = 0; k < 4; k++) c[i][j][k] = 0.0f;

    uint4 ah[2][2], al[2][2];
    uint2 bh[2][2], bl[2][2];
    {
        int af = ((akf0 + kfl0) * 4 + mg * 2) * 32 + lane;
        ah[0][0] = Aph[af]; ah[0][1] = Aph[af + 32];
        al[0][0] = Apl[af]; al[0][1] = Apl[af + 32];
        int wf = (kfl0 * 2) * 32 + lane;
        bh[0][0] = Wh[wf]; bh[0][1] = Wh[wf + 32];
        bl[0][0] = Wl[wf]; bl[0][1] = Wl[wf + 32];
    }
#pragma unroll
    for (int s = 0; s < KF; s++) {
        const int cur = s & 1, nxt = cur ^ 1;
        if (s + 1 < KF) {
            int af = ((akf0 + kfl0 + s + 1) * 4 + mg * 2) * 32 + lane;
            ah[nxt][0] = Aph[af]; ah[nxt][1] = Aph[af + 32];
            al[nxt][0] = Apl[af]; al[nxt][1] = Apl[af + 32];
            int wf = ((kfl0 + s + 1) * 2) * 32 + lane;
            bh[nxt][0] = Wh[wf]; bh[nxt][1] = Wh[wf + 32];
            bl[nxt][0] = Wl[wf]; bl[nxt][1] = Wl[wf + 32];
        }
#pragma unroll
        for (int mf = 0; mf < 2; mf++)
#pragma unroll
            for (int nf = 0; nf < 2; nf++) {
                mma16816(c[mf][nf], &ah[cur][mf].x, &bh[cur][nf].x);
                mma16816(c[mf][nf], &al[cur][mf].x, &bh[cur][nf].x);
                mma16816(c[mf][nf], &ah[cur][mf].x, &bl[cur][nf].x);
            }
    }
    const int r = lane >> 2, c2 = (lane & 3) * 2;
#pragma unroll
    for (int mf = 0; mf < 2; mf++)
#pragma unroll
        for (int nf = 0; nf < 2; nf++) {
            float* p = scr + (kg * 64 + mg * 32 + mf * 16 + r) * 20 + nf * 8 + c2;
            *(float2*)p = make_float2(c[mf][nf][0], c[mf][nf][1]);
            *(float2*)(p + 8 * 20) = make_float2(c[mf][nf][2], c[mf][nf][3]);
        }
}

__device__ __forceinline__ void reduce4(const float* __restrict__ scr,
                                        int m, int nq, float* pre)
{
#pragma unroll
    for (int kg = 0; kg < 4; kg++) {
        float4 a = *(const float4*)(scr + kg * 1280 + m * 20 + nq);
        pre[0] += a.x; pre[1] += a.y; pre[2] += a.z; pre[3] += a.w;
    }
}

// pack sbuf[64][20] (16 cols of values) into A-frag planes at kf = jkf.
// 8 warps: warps 0-3 write the hi plane (mf = wid), warps 4-7 the lo plane.
__device__ __forceinline__ void pack16(const float* __restrict__ sbuf,
                                       uint4* __restrict__ dsth,
                                       uint4* __restrict__ dstl,
                                       int jkf, int wid, int lane)
{
    if (wid < 8) {
        const int mf = wid & 3;
        const int r = lane >> 2, c2 = (lane & 3) * 2;
        const float* p = sbuf + (mf * 16 + r) * 20 + c2;
        uint32_t h0, h1, h2, h3, l0, l1, l2, l3;
        splitp(p[0], p[1], h0, l0);
        splitp(p[160], p[161], h1, l1);
        splitp(p[8], p[9], h2, l2);
        splitp(p[168], p[169], h3, l3);
        const int fi = (jkf * 4 + mf) * 32 + lane;
        if (wid < 4) dsth[fi] = make_uint4(h0, h1, h2, h3);
        else         dstl[fi] = make_uint4(l0, l1, l2, l3);
    }
}

__global__ void __launch_bounds__(256, 1) gru_step_kernel(
    const float* __restrict__ h0in,
    const float* __restrict__ Whz, const float* __restrict__ Whr,
    const float* __restrict__ Whh,
    const float* __restrict__ Whz_b, const float* __restrict__ Whr_b,
    const float* __restrict__ Whh_b,
    const float* __restrict__ Wiz_b, const float* __restrict__ Wir_b,
    const float* __restrict__ Wih_b,
    const void* __restrict__ lengths,
    float* __restrict__ out, int write_last)
{
    extern __shared__ char sm[];
    uint2* W1h = (uint2*)(sm + W1_H);
    uint2* W1l = (uint2*)(sm + W1_L);
    uint2* W2h = (uint2*)(sm + W2_H);
    uint2* W2l = (uint2*)(sm + W2_L);
    float* scr = (float*)(sm + PB_SCR);
    float* sbuf = (float*)(sm + PB_SBUF);
    float* bia = (float*)(sm + PB_BIA);     // [0:16) gate, [16:32) cand
    int* slen = (int*)(sm + PB_SLEN);

    const int tid = threadIdx.x, wid = tid >> 5, lane = tid & 31;
    const int b = blockIdx.x;
    const int is_zc = (b < 64);
    const int j = b & 63;
    const int gn0 = j * 16;

    const float* Wgate = is_zc ? Whz : Whr;
    const float* bgh   = is_zc ? Whz_b : Whr_b;
    const float* bgi   = is_zc ? Wiz_b : Wir_b;
    const int koff = is_zc ? 512 : 0;   // c-half K offset

    // ---- pack gate W slice (16 cols x K1024) : 128 frags ----
#pragma unroll 4
    for (int it = 0; it < 16; it++) {
        int idx = tid + (it << 8);
        int frag = idx >> 5, l = idx & 31;
        int kf = frag >> 1, nf = frag & 1;
        int n = nf * 8 + (l >> 2), k = kf * 16 + (l & 3) * 2;
        const float* src = Wgate + (size_t)(gn0 + n) * NH + k;
        float2 q0 = *(const float2*)src;
        float2 q1 = *(const float2*)(src + 8);
        uint32_t h0, h1, lo0, lo1;
        splitp(q0.x, q0.y, h0, lo0); splitp(q1.x, q1.y, h1, lo1);
        W1h[frag * 32 + l] = make_uint2(h0, h1);
        W1l[frag * 32 + l] = make_uint2(lo0, lo1);
    }
    // ---- pack c-half W slice (16 cols x K512) : 64 frags ----
#pragma unroll 4
    for (int it = 0; it < 8; it++) {
        int idx = tid + (it << 8);
        int frag = idx >> 5, l = idx & 31;
        int kf = frag >> 1, nf = frag & 1;
        int n = nf * 8 + (l >> 2), k = koff + kf * 16 + (l & 3) * 2;
        const float* src = Whh + (size_t)(gn0 + n) * NH + k;
        float2 q0 = *(const float2*)src;
        float2 q1 = *(const float2*)(src + 8);
        uint32_t h0, h1, lo0, lo1;
        splitp(q0.x, q0.y, h0, lo0); splitp(q1.x, q1.y, h1, lo1);
        W2h[frag * 32 + l] = make_uint2(h0, h1);
        W2l[frag * 32 + l] = make_uint2(lo0, lo1);
    }
    if (tid < 16) {
        bia[tid] = bgh[gn0 + tid] + bgi[gn0 + tid];
        bia[16 + tid] = Whh_b[gn0 + tid] + Wih_b[gn0 + tid];
    }
    {   // lengths dtype auto-detect (int64 -> high word of elem0 is 0)
        const int* L32 = (const int*)lengths;
        int is64 = (L32[1] == 0);
        if (tid < BATCH)
            slen[tid] = is64 ? (int)((const long long*)lengths)[tid] : L32[tid];
    }

    const int m = tid >> 2, nq = (tid & 3) * 4;
    float hreg[4];

    if (is_zc) {
        // init h: registers + plain fp32 + frag planes parity 0
        const float* src = h0in + (size_t)m * NH + gn0 + nq;
        float4 v = *(const float4*)src;
        hreg[0] = v.x; hreg[1] = v.y; hreg[2] = v.z; hreg[3] = v.w;
        *(float4*)(g_h32 + (size_t)m * NH + gn0 + nq) = v;
        *(float4*)(sbuf + m * 20 + nq) = v;
        __syncthreads();
        pack16(sbuf, g_hhf[0], g_hlf[0], j, wid, lane);
        __syncthreads();
        if (tid == 0) st_rel(&g_fh[j], 0);
    } else {
        __syncthreads();
    }

    const int sl = slen[m];
    const size_t GATE = (size_t)TSTEPS * BATCH * NH;
    const size_t xrow = (size_t)m * NH + gn0 + nq;

    if (is_zc) {
        const float* Xz = g_X + xrow;               // gate 0
        const float* Xh = g_X + 2 * GATE + xrow;    // gate 2
        float* cpart = g_cpart + j * 1024 + m * 16 + nq;
        for (int t = 0; t < TSTEPS; t++) {
            float4 xz = *(const float4*)(Xz + (size_t)t * BATCH * NH);
            float4 xh = *(const float4*)(Xh + (size_t)t * BATCH * NH);
            // ---- z gemm ----
            block_wait64(g_fh, t);
            gemm_t<16>(g_hhf[t & 1], g_hlf[t & 1], 0, W1h, W1l, scr, wid, lane);
            __syncthreads();
            float zv[4] = {xz.x + bia[nq], xz.y + bia[nq + 1],
                           xz.z + bia[nq + 2], xz.w + bia[nq + 3]};
            reduce4(scr, m, nq, zv);
#pragma unroll
            for (int jj = 0; jj < 4; jj++) zv[jj] = 1.0f / (1.0f + expf(-zv[jj]));
            // ---- c gemm, high K half (wait also closes scr-consume window) ----
            block_wait32(g_frh + 32, t + 1);
            gemm_t<8>(g_rhhf, g_rhlf, 32, W2h, W2l, scr, wid, lane);
            __syncthreads();
            // ---- merge with partner's low-K partial, finish step ----
            block_wait1(&g_fcp[j], t + 1);
            float4 cp = *(const float4*)cpart;
            float pre[4] = {xh.x + bia[16 + nq] + cp.x, xh.y + bia[16 + nq + 1] + cp.y,
                            xh.z + bia[16 + nq + 2] + cp.z, xh.w + bia[16 + nq + 3] + cp.w};
            reduce4(scr, m, nq, pre);
            float hn[4];
#pragma unroll
            for (int jj = 0; jj < 4; jj++) {
                float hc = tanhf(pre[jj]);
                float v = (1.0f - zv[jj]) * hreg[jj] + zv[jj] * hc;
                if (t >= sl) v = hreg[jj];
                hreg[jj] = v;
                hn[jj] = v;
            }
            float4 hv = make_float4(hn[0], hn[1], hn[2], hn[3]);
            *(float4*)(g_h32 + (size_t)m * NH + gn0 + nq) = hv;
            *(float4*)(sbuf + m * 20 + nq) = hv;
            __syncthreads();
            pack16(sbuf, g_hhf[(t + 1) & 1], g_hlf[(t + 1) & 1], j, wid, lane);
            __syncthreads();
            if (tid == 0) st_rel(&g_fh[j], t + 1);
            // out store deferred past the publish — off the critical hop
            *(float4*)(out + (size_t)t * BATCH * NH + xrow) = hv;
        }
        if (write_last) {
            *(float4*)(out + (size_t)TSTEPS * BATCH * NH + xrow) =
                make_float4(hreg[0], hreg[1], hreg[2], hreg[3]);
        }
    } else {
        const float* Xr = g_X + GATE + xrow;        // gate 1
        float* cpart = g_cpart + j * 1024 + m * 16 + nq;
        for (int t = 0; t < TSTEPS; t++) {
            float4 xr = *(const float4*)(Xr + (size_t)t * BATCH * NH);
            // ---- r gemm ----
            block_wait64(g_fh, t);
            gemm_t<16>(g_hhf[t & 1], g_hlf[t & 1], 0, W1h, W1l, scr, wid, lane);
            __syncthreads();
            float pre[4] = {xr.x + bia[nq], xr.y + bia[nq + 1],
                            xr.z + bia[nq + 2], xr.w + bia[nq + 3]};
            reduce4(scr, m, nq, pre);
            float4 hp = *(const float4*)(g_h32 + (size_t)m * NH + gn0 + nq);
            float hv[4] = {hp.x, hp.y, hp.z, hp.w};
            float rh[4];
#pragma unroll
            for (int jj = 0; jj < 4; jj++) {
                float s = 1.0f / (1.0f + expf(-pre[jj]));
                rh[jj] = s * hv[jj];
            }
            *(float4*)(sbuf + m * 20 + nq) = make_float4(rh[0], rh[1], rh[2], rh[3]);
            __syncthreads();
            pack16(sbuf, g_rhhf, g_rhlf, j, wid, lane);
            __syncthreads();
            if (tid == 0) st_rel(&g_frh[j], t + 1);
            // ---- c gemm, low K half ----
            block_wait32(g_frh, t + 1);
            gemm_t<8>(g_rhhf, g_rhlf, 0, W2h, W2l, scr, wid, lane);
            __syncthreads();
            float part[4] = {0.0f, 0.0f, 0.0f, 0.0f};
            reduce4(scr, m, nq, part);
            *(float4*)cpart = make_float4(part[0], part[1], part[2], part[3]);
            __syncthreads();
            if (tid == 0) st_rel(&g_fcp[j], t + 1);
        }
    }
}

// ============================= launch =======================================
extern "C" void kernel_launch(void* const* d_in, const int* in_sizes, int n_in,
                              void* d_out, int out_size)
{
    const float* input = (const float*)d_in[0];
    const float* h0    = (const float*)d_in[1];
    const float* Wiz_w = (const float*)d_in[2];
    const float* Wiz_b = (const float*)d_in[3];
    const float* Wir_w = (const float*)d_in[4];
    const float* Wir_b = (const float*)d_in[5];
    const float* Wih_w = (const float*)d_in[6];
    const float* Wih_b = (const float*)d_in[7];
    const float* Whz_w = (const float*)d_in[8];
    const float* Whz_b = (const float*)d_in[9];
    const float* Whr_w = (const float*)d_in[10];
    const float* Whr_b = (const float*)d_in[11];
    const float* Whh_w = (const float*)d_in[12];
    const float* Whh_b = (const float*)d_in[13];
    const void*  lengths = d_in[14];

    cudaFuncSetAttribute(input_proj_kernel,
                         cudaFuncAttributeMaxDynamicSharedMemorySize, PA_SMEM);
    cudaFuncSetAttribute(gru_step_kernel,
                         cudaFuncAttributeMaxDynamicSharedMemorySize, PB_SMEM);

    init_misc_kernel<<<1, 64>>>();
    input_proj_kernel<<<256 * 24, 256, PA_SMEM>>>(input, Wiz_w, Wir_w, Wih_w);

    int write_last = (out_size >= TSTEPS * BATCH * NH + BATCH * NH) ? 1 : 0;
    gru_step_kernel<<<NBLK, 256, PB_SMEM>>>(
        h0, Whz_w, Whr_w, Whh_w, Whz_b, Whr_b, Whh_b,
        Wiz_b, Wir_b, Wih_b, lengths, (float*)d_out, write_last);
}

// round 12
// speedup vs baseline: 1.2210x; 1.1045x over previous
#include <cuda_runtime.h>
#include <cuda_bf16.h>
#include <cstdint>
#include <math.h>

#define TSTEPS 512
#define BATCH  64
#define NIN    512
#define NH     1024
#define NBLK   128

// ============================ global scratch ================================
__device__ float g_X[(size_t)3 * TSTEPS * BATCH * NH];   // input projections
// A-operand planes, frag order per half: (kf*2+mf)*32+lane, kf 0..63, mf 0..1
__device__ uint4 g_hhf[2][2][4096], g_hlf[2][2][4096];   // h planes [parity][half]
__device__ uint4 g_rhhf[2][4096], g_rhlf[2][4096];       // r*h planes [half]
__device__ int g_fh[128], g_frh[128];                    // flags [j + 64*half]

// ============================ helpers =======================================
__device__ __forceinline__ uint32_t bfpack(float x, float y) {
    __nv_bfloat162 t = __floats2bfloat162_rn(x, y);
    return *(uint32_t*)&t;
}
__device__ __forceinline__ void splitp(float x, float y, uint32_t& hi, uint32_t& lo) {
    float hx = __bfloat162float(__float2bfloat16(x));
    float hy = __bfloat162float(__float2bfloat16(y));
    hi = bfpack(hx, hy);
    lo = bfpack(x - hx, y - hy);
}
__device__ __forceinline__ void mma16816(float* c, const uint32_t* a, const uint32_t* b) {
    asm volatile("mma.sync.aligned.m16n8k16.row.col.f32.bf16.bf16.f32 "
        "{%0,%1,%2,%3},{%4,%5,%6,%7},{%8,%9},{%0,%1,%2,%3};"
        : "+f"(c[0]), "+f"(c[1]), "+f"(c[2]), "+f"(c[3])
        : "r"(a[0]), "r"(a[1]), "r"(a[2]), "r"(a[3]), "r"(b[0]), "r"(b[1]));
}
__device__ __forceinline__ int ld_acq(const int* p) {
    int v;
    asm volatile("ld.acquire.gpu.global.s32 %0, [%1];" : "=r"(v) : "l"(p) : "memory");
    return v;
}
__device__ __forceinline__ void st_rel(int* p, int v) {
    asm volatile("st.release.gpu.global.s32 [%0], %1;" :: "l"(p), "r"(v) : "memory");
}
// single-warp polling of 64 flags (warp 0), block released by syncthreads
__device__ __forceinline__ void block_wait64(const int* flags, int target) {
    if (threadIdx.x < 32) {
        const int* p0 = flags + threadIdx.x;
        const int* p1 = flags + 32 + threadIdx.x;
        while (!__all_sync(0xFFFFFFFFu,
                           (ld_acq(p0) >= target) && (ld_acq(p1) >= target)))
            __nanosleep(60);
    }
    __syncthreads();
}

// =================== init: reset flags each launch ==========================
__global__ void init_misc_kernel() {
    int i = threadIdx.x;
    if (i < 128) { g_fh[i] = -1; g_frh[i] = -1; }
}

// ======================= phase A: input projections =========================
#define PA_AH 0
#define PA_AL 32768
#define PA_WH 65536
#define PA_WL 98304
#define PA_SMEM 131072

__global__ void __launch_bounds__(256) input_proj_kernel(
    const float* __restrict__ input,
    const float* __restrict__ Wiz, const float* __restrict__ Wir,
    const float* __restrict__ Wih)
{
    extern __shared__ char sm[];
    uint4* Ah = (uint4*)(sm + PA_AH);
    uint4* Al = (uint4*)(sm + PA_AL);
    uint2* Wh = (uint2*)(sm + PA_WH);
    uint2* Wl = (uint2*)(sm + PA_WL);
    const int tid = threadIdx.x, wid = tid >> 5, lane = tid & 31;
    const int ntile = blockIdx.x % 24, mtile = blockIdx.x / 24;
    const int gate = ntile >> 3, n0g = (ntile & 7) * 128, m0 = mtile * 128;
    const float* W = (gate == 0) ? Wiz : ((gate == 1) ? Wir : Wih);
    const int mg = wid & 3, ng = wid >> 2;

    float c[2][8][4];
#pragma unroll
    for (int i = 0; i < 2; i++)
#pragma unroll
        for (int j = 0; j < 8; j++)
#pragma unroll
            for (int k = 0; k < 4; k++) c[i][j][k] = 0.0f;

    for (int ch = 0; ch < 4; ch++) {
        const int k0 = ch * 128;
        __syncthreads();
#pragma unroll
        for (int it = 0; it < 8; it++) {
            int idx = tid + (it << 8);
            int frag = idx >> 5, l = idx & 31;
            int kf = frag >> 3, mf = frag & 7;
            int r = l >> 2, c2 = (l & 3) * 2;
            const float* src = input + (size_t)(m0 + mf * 16 + r) * NIN + k0 + kf * 16 + c2;
            float2 p0 = *(const float2*)(src);
            float2 p1 = *(const float2*)(src + 8 * NIN);
            float2 p2 = *(const float2*)(src + 8);
            float2 p3 = *(const float2*)(src + 8 * NIN + 8);
            uint32_t h0, h1, h2, h3, lo0, lo1, lo2, lo3;
            splitp(p0.x, p0.y, h0, lo0); splitp(p1.x, p1.y, h1, lo1);
            splitp(p2.x, p2.y, h2, lo2); splitp(p3.x, p3.y, h3, lo3);
            Ah[frag * 32 + l] = make_uint4(h0, h1, h2, h3);
            Al[frag * 32 + l] = make_uint4(lo0, lo1, lo2, lo3);
        }
#pragma unroll
        for (int it = 0; it < 16; it++) {
            int idx = tid + (it << 8);
            int frag = idx >> 5, l = idx & 31;
            int kf = frag >> 4, nf = frag & 15;
            int n = nf * 8 + (l >> 2), k = kf * 16 + (l & 3) * 2;
            const float* src = W + (size_t)(n0g + n) * NIN + k0 + k;
            float2 q0 = *(const float2*)src;
            float2 q1 = *(const float2*)(src + 8);
            uint32_t h0, h1, lo0, lo1;
            splitp(q0.x, q0.y, h0, lo0); splitp(q1.x, q1.y, h1, lo1);
            Wh[frag * 32 + l] = make_uint2(h0, h1);
            Wl[frag * 32 + l] = make_uint2(lo0, lo1);
        }
        __syncthreads();
#pragma unroll 2
        for (int s = 0; s < 8; s++) {
            uint4 ah[2], al[2];
            uint2 bh[8], bl[8];
            ah[0] = Ah[(s * 8 + mg * 2 + 0) * 32 + lane];
            ah[1] = Ah[(s * 8 + mg * 2 + 1) * 32 + lane];
            al[0] = Al[(s * 8 + mg * 2 + 0) * 32 + lane];
            al[1] = Al[(s * 8 + mg * 2 + 1) * 32 + lane];
#pragma unroll
            for (int nf = 0; nf < 8; nf++) {
                bh[nf] = Wh[(s * 16 + ng * 8 + nf) * 32 + lane];
                bl[nf] = Wl[(s * 16 + ng * 8 + nf) * 32 + lane];
            }
#pragma unroll
            for (int mf = 0; mf < 2; mf++)
#pragma unroll
                for (int nf = 0; nf < 8; nf++) {
                    mma16816(c[mf][nf], &ah[mf].x, &bh[nf].x);
                    mma16816(c[mf][nf], &al[mf].x, &bh[nf].x);
                    mma16816(c[mf][nf], &ah[mf].x, &bl[nf].x);
                }
        }
    }
    const int r = lane >> 2, c2 = (lane & 3) * 2;
#pragma unroll
    for (int mf = 0; mf < 2; mf++)
#pragma unroll
        for (int nf = 0; nf < 8; nf++) {
            size_t row = (size_t)(m0 + (mg * 2 + mf) * 16 + r);
            size_t base = ((size_t)gate * TSTEPS * BATCH + row) * NH
                        + n0g + (ng * 8 + nf) * 8 + c2;
            *(float2*)(g_X + base) = make_float2(c[mf][nf][0], c[mf][nf][1]);
            *(float2*)(g_X + base + (size_t)8 * NH) = make_float2(c[mf][nf][2], c[mf][nf][3]);
        }
}

// ======================= phase B: persistent GRU ============================
// 128 blocks = 2 independent chains (half = batch rows 0-31 / 32-63).
// Block (half, j): 32 rows x 16 cols of z, r, rh, candidate, h. 2 hops/step.
#define W_ZH 0          // 128 frags x 32 x 8B = 32768 per plane
#define W_ZL 32768
#define W_RH 65536
#define W_RL 98304
#define W_CH 131072
#define W_CL 163840
#define PB_SCRZ 196608  // float[4][32][20] = 10240
#define PB_SCRR 206848  // float[4][32][20] = 10240
#define PB_SBUF 217088  // float[32][20]    =  2560
#define PB_BIA  219648  // float[48]: z|r|c
#define PB_SLEN 219840  // int[32]
#define PB_SMEM 220160

// pack full-K W slice (16 cols x 1024) into 128 B-frag-order split frags
__device__ __forceinline__ void packW(const float* __restrict__ W, int gn0,
                                      uint2* __restrict__ Dh, uint2* __restrict__ Dl,
                                      int tid)
{
#pragma unroll 4
    for (int it = 0; it < 16; it++) {
        int idx = tid + (it << 8);
        int frag = idx >> 5, l = idx & 31;
        int kf = frag >> 1, nf = frag & 1;
        int n = nf * 8 + (l >> 2), k = kf * 16 + (l & 3) * 2;
        const float* src = W + (size_t)(gn0 + n) * NH + k;
        float2 q0 = *(const float2*)src;
        float2 q1 = *(const float2*)(src + 8);
        uint32_t h0, h1, lo0, lo1;
        splitp(q0.x, q0.y, h0, lo0); splitp(q1.x, q1.y, h1, lo1);
        Dh[frag * 32 + l] = make_uint2(h0, h1);
        Dl[frag * 32 + l] = make_uint2(lo0, lo1);
    }
}

// fused z+r gemm: C[32x16] x2 = A[32x1024] @ {Wz,Wr}^T. A read once.
// 8 warps: mf = wid&1 (16 rows), kg = wid>>1 (4 groups x 16 kf). 3-term.
__device__ __forceinline__ void gemm_zr(const uint4* __restrict__ Aph,
                                        const uint4* __restrict__ Apl,
                                        const uint2* __restrict__ Wzh, const uint2* __restrict__ Wzl,
                                        const uint2* __restrict__ Wrh, const uint2* __restrict__ Wrl,
                                        float* __restrict__ scrz, float* __restrict__ scrr,
                                        int wid, int lane)
{
    const int mf = wid & 1, kg = wid >> 1;
    const int kf0 = kg * 16;
    float cz[2][4], cr[2][4];
#pragma unroll
    for (int j = 0; j < 2; j++)
#pragma unroll
        for (int k = 0; k < 4; k++) { cz[j][k] = 0.0f; cr[j][k] = 0.0f; }

    uint4 ah[2], al[2];
    uint2 bzh[2][2], bzl[2][2], brh[2][2], brl[2][2];
    {
        int af = (kf0 * 2 + mf) * 32 + lane;
        ah[0] = Aph[af]; al[0] = Apl[af];
        int wf = (kf0 * 2) * 32 + lane;
        bzh[0][0] = Wzh[wf]; bzh[0][1] = Wzh[wf + 32];
        bzl[0][0] = Wzl[wf]; bzl[0][1] = Wzl[wf + 32];
        brh[0][0] = Wrh[wf]; brh[0][1] = Wrh[wf + 32];
        brl[0][0] = Wrl[wf]; brl[0][1] = Wrl[wf + 32];
    }
#pragma unroll
    for (int s = 0; s < 16; s++) {
        const int cur = s & 1, nxt = cur ^ 1;
        if (s < 15) {
            int kf = kf0 + s + 1;
            int af = (kf * 2 + mf) * 32 + lane;
            ah[nxt] = Aph[af]; al[nxt] = Apl[af];
            int wf = (kf * 2) * 32 + lane;
            bzh[nxt][0] = Wzh[wf]; bzh[nxt][1] = Wzh[wf + 32];
            bzl[nxt][0] = Wzl[wf]; bzl[nxt][1] = Wzl[wf + 32];
            brh[nxt][0] = Wrh[wf]; brh[nxt][1] = Wrh[wf + 32];
            brl[nxt][0] = Wrl[wf]; brl[nxt][1] = Wrl[wf + 32];
        }
#pragma unroll
        for (int nf = 0; nf < 2; nf++) {
            mma16816(cz[nf], &ah[cur].x, &bzh[cur][nf].x);
            mma16816(cz[nf], &al[cur].x, &bzh[cur][nf].x);
            mma16816(cz[nf], &ah[cur].x, &bzl[cur][nf].x);
            mma16816(cr[nf], &ah[cur].x, &brh[cur][nf].x);
            mma16816(cr[nf], &al[cur].x, &brh[cur][nf].x);
            mma16816(cr[nf], &ah[cur].x, &brl[cur][nf].x);
        }
    }
    const int r = lane >> 2, c2 = (lane & 3) * 2;
#pragma unroll
    for (int nf = 0; nf < 2; nf++) {
        int off = kg * 640 + (mf * 16 + r) * 20 + nf * 8 + c2;
        *(float2*)(scrz + off) = make_float2(cz[nf][0], cz[nf][1]);
        *(float2*)(scrz + off + 8 * 20) = make_float2(cz[nf][2], cz[nf][3]);
        *(float2*)(scrr + off) = make_float2(cr[nf][0], cr[nf][1]);
        *(float2*)(scrr + off + 8 * 20) = make_float2(cr[nf][2], cr[nf][3]);
    }
}

// candidate gemm: C[32x16] = RH[32x1024] @ Wc^T
__device__ __forceinline__ void gemm_c(const uint4* __restrict__ Aph,
                                       const uint4* __restrict__ Apl,
                                       const uint2* __restrict__ Wh,
                                       const uint2* __restrict__ Wl,
                                       float* __restrict__ scr,
                                       int wid, int lane)
{
    const int mf = wid & 1, kg = wid >> 1;
    const int kf0 = kg * 16;
    float c[2][4];
#pragma unroll
    for (int j = 0; j < 2; j++)
#pragma unroll
        for (int k = 0; k < 4; k++) c[j][k] = 0.0f;

    uint4 ah[2], al[2];
    uint2 bh[2][2], bl[2][2];
    {
        int af = (kf0 * 2 + mf) * 32 + lane;
        ah[0] = Aph[af]; al[0] = Apl[af];
        int wf = (kf0 * 2) * 32 + lane;
        bh[0][0] = Wh[wf]; bh[0][1] = Wh[wf + 32];
        bl[0][0] = Wl[wf]; bl[0][1] = Wl[wf + 32];
    }
#pragma unroll
    for (int s = 0; s < 16; s++) {
        const int cur = s & 1, nxt = cur ^ 1;
        if (s < 15) {
            int kf = kf0 + s + 1;
            int af = (kf * 2 + mf) * 32 + lane;
            ah[nxt] = Aph[af]; al[nxt] = Apl[af];
            int wf = (kf * 2) * 32 + lane;
            bh[nxt][0] = Wh[wf]; bh[nxt][1] = Wh[wf + 32];
            bl[nxt][0] = Wl[wf]; bl[nxt][1] = Wl[wf + 32];
        }
#pragma unroll
        for (int nf = 0; nf < 2; nf++) {
            mma16816(c[nf], &ah[cur].x, &bh[cur][nf].x);
            mma16816(c[nf], &al[cur].x, &bh[cur][nf].x);
            mma16816(c[nf], &ah[cur].x, &bl[cur][nf].x);
        }
    }
    const int r = lane >> 2, c2 = (lane & 3) * 2;
#pragma unroll
    for (int nf = 0; nf < 2; nf++) {
        int off = kg * 640 + (mf * 16 + r) * 20 + nf * 8 + c2;
        *(float2*)(scr + off) = make_float2(c[nf][0], c[nf][1]);
        *(float2*)(scr + off + 8 * 20) = make_float2(c[nf][2], c[nf][3]);
    }
}

// pack sbuf[32][20] (16 cols) into 2 A-frags at kf = j (warps 0-1)
__device__ __forceinline__ void pack2(const float* __restrict__ sbuf,
                                      uint4* __restrict__ dsth,
                                      uint4* __restrict__ dstl,
                                      int jkf, int wid, int lane)
{
    if (wid < 2) {
        const int mf = wid;
        const int r = lane >> 2, c2 = (lane & 3) * 2;
        const float* p = sbuf + (mf * 16 + r) * 20 + c2;
        uint32_t h0, h1, h2, h3, l0, l1, l2, l3;
        splitp(p[0], p[1], h0, l0);
        splitp(p[160], p[161], h1, l1);
        splitp(p[8], p[9], h2, l2);
        splitp(p[168], p[169], h3, l3);
        const int fi = (jkf * 2 + mf) * 32 + lane;
        dsth[fi] = make_uint4(h0, h1, h2, h3);
        dstl[fi] = make_uint4(l0, l1, l2, l3);
    }
}

__global__ void __launch_bounds__(256, 1) gru_step_kernel(
    const float* __restrict__ h0in,
    const float* __restrict__ Whz, const float* __restrict__ Whr,
    const float* __restrict__ Whh,
    const float* __restrict__ Whz_b, const float* __restrict__ Whr_b,
    const float* __restrict__ Whh_b,
    const float* __restrict__ Wiz_b, const float* __restrict__ Wir_b,
    const float* __restrict__ Wih_b,
    const void* __restrict__ lengths,
    float* __restrict__ out, int write_last)
{
    extern __shared__ char sm[];
    uint2* Wzh = (uint2*)(sm + W_ZH);
    uint2* Wzl = (uint2*)(sm + W_ZL);
    uint2* Wrh = (uint2*)(sm + W_RH);
    uint2* Wrl = (uint2*)(sm + W_RL);
    uint2* Wch = (uint2*)(sm + W_CH);
    uint2* Wcl = (uint2*)(sm + W_CL);
    float* scrz = (float*)(sm + PB_SCRZ);
    float* scrr = (float*)(sm + PB_SCRR);
    float* sbuf = (float*)(sm + PB_SBUF);
    float* bia = (float*)(sm + PB_BIA);     // [0:16) z, [16:32) r, [32:48) c
    int* slen = (int*)(sm + PB_SLEN);

    const int tid = threadIdx.x, wid = tid >> 5, lane = tid & 31;
    const int b = blockIdx.x;
    const int half = b >> 6;
    const int j = b & 63;
    const int gn0 = j * 16;
    const int row0 = half * 32;

    packW(Whz, gn0, Wzh, Wzl, tid);
    packW(Whr, gn0, Wrh, Wrl, tid);
    packW(Whh, gn0, Wch, Wcl, tid);
    if (tid < 16) {
        bia[tid]      = Whz_b[gn0 + tid] + Wiz_b[gn0 + tid];
        bia[16 + tid] = Whr_b[gn0 + tid] + Wir_b[gn0 + tid];
        bia[32 + tid] = Whh_b[gn0 + tid] + Wih_b[gn0 + tid];
    }
    {   // lengths dtype auto-detect (int64 -> high word of elem0 is 0)
        const int* L32 = (const int*)lengths;
        int is64 = (L32[1] == 0);
        if (tid < 32) {
            int rr = row0 + tid;
            slen[tid] = is64 ? (int)((const long long*)lengths)[rr] : L32[rr];
        }
    }

    const int m = tid >> 3;          // 0..31
    const int nq = (tid & 7) * 2;    // 0..14
    const size_t xrow = (size_t)(row0 + m) * NH + gn0 + nq;
    float h0r, h1r;                  // local h tile (2 elems/thread)

    {   // init h
        float2 v = *(const float2*)(h0in + xrow);
        h0r = v.x; h1r = v.y;
        *(float2*)(sbuf + m * 20 + nq) = v;
        __syncthreads();
        pack2(sbuf, g_hhf[0][half], g_hlf[0][half], j, wid, lane);
        __syncthreads();
        if (tid == 0) { __threadfence(); st_rel(&g_fh[half * 64 + j], 0); }
    }

    const int sl = slen[m];
    const size_t GATE = (size_t)TSTEPS * BATCH * NH;
    const float* Xz = g_X + xrow;
    const float* Xr = g_X + GATE + xrow;
    const float* Xh = g_X + 2 * GATE + xrow;
    const int* fhb = g_fh + half * 64;
    const int* frhb = g_frh + half * 64;
    const uint4* hhfp[2] = {g_hhf[0][half], g_hhf[1][half]};
    const uint4* hlfp[2] = {g_hlf[0][half], g_hlf[1][half]};
    uint4* rhh = g_rhhf[half];
    uint4* rhl = g_rhlf[half];

    for (int t = 0; t < TSTEPS; t++) {
        float2 xz = *(const float2*)(Xz + (size_t)t * BATCH * NH);
        float2 xr = *(const float2*)(Xr + (size_t)t * BATCH * NH);
        float2 xh = *(const float2*)(Xh + (size_t)t * BATCH * NH);
        // ---- fused z+r gemm ----
        block_wait64(fhb, t);
        gemm_zr(hhfp[t & 1], hlfp[t & 1], Wzh, Wzl, Wrh, Wrl, scrz, scrr, wid, lane);
        __syncthreads();
        // ---- epi1: z (registers), rh -> sbuf ----
        float z0 = bia[nq] + xz.x, z1 = bia[nq + 1] + xz.y;
        float r0 = bia[16 + nq] + xr.x, r1 = bia[16 + nq + 1] + xr.y;
#pragma unroll
        for (int kg = 0; kg < 4; kg++) {
            float2 az = *(const float2*)(scrz + kg * 640 + m * 20 + nq);
            float2 ar = *(const float2*)(scrr + kg * 640 + m * 20 + nq);
            z0 += az.x; z1 += az.y;
            r0 += ar.x; r1 += ar.y;
        }
        z0 = 1.0f / (1.0f + expf(-z0));
        z1 = 1.0f / (1.0f + expf(-z1));
        r0 = 1.0f / (1.0f + expf(-r0));
        r1 = 1.0f / (1.0f + expf(-r1));
        *(float2*)(sbuf + m * 20 + nq) = make_float2(r0 * h0r, r1 * h1r);
        __syncthreads();
        pack2(sbuf, rhh, rhl, j, wid, lane);
        __syncthreads();
        if (tid == 0) { __threadfence(); st_rel(&g_frh[half * 64 + j], t + 1); }
        // ---- candidate gemm ----
        block_wait64(frhb, t + 1);
        gemm_c(rhh, rhl, Wch, Wcl, scrz, wid, lane);
        __syncthreads();
        // ---- epi2: update h ----
        float p0 = bia[32 + nq] + xh.x, p1 = bia[32 + nq + 1] + xh.y;
#pragma unroll
        for (int kg = 0; kg < 4; kg++) {
            float2 a = *(const float2*)(scrz + kg * 640 + m * 20 + nq);
            p0 += a.x; p1 += a.y;
        }
        float hn0 = (1.0f - z0) * h0r + z0 * tanhf(p0);
        float hn1 = (1.0f - z1) * h1r + z1 * tanhf(p1);
        if (t >= sl) { hn0 = h0r; hn1 = h1r; }
        h0r = hn0; h1r = hn1;
        *(float2*)(out + (size_t)t * BATCH * NH + xrow) = make_float2(hn0, hn1);
        *(float2*)(sbuf + m * 20 + nq) = make_float2(hn0, hn1);
        __syncthreads();
        pack2(sbuf, g_hhf[(t + 1) & 1][half], g_hlf[(t + 1) & 1][half], j, wid, lane);
        __syncthreads();
        if (tid == 0) { __threadfence(); st_rel(&g_fh[half * 64 + j], t + 1); }
    }
    if (write_last) {
        *(float2*)(out + (size_t)TSTEPS * BATCH * NH + xrow) = make_float2(h0r, h1r);
    }
}

// ============================= launch =======================================
extern "C" void kernel_launch(void* const* d_in, const int* in_sizes, int n_in,
                              void* d_out, int out_size)
{
    const float* input = (const float*)d_in[0];
    const float* h0    = (const float*)d_in[1];
    const float* Wiz_w = (const float*)d_in[2];
    const float* Wiz_b = (const float*)d_in[3];
    const float* Wir_w = (const float*)d_in[4];
    const float* Wir_b = (const float*)d_in[5];
    const float* Wih_w = (const float*)d_in[6];
    const float* Wih_b = (const float*)d_in[7];
    const float* Whz_w = (const float*)d_in[8];
    const float* Whz_b = (const float*)d_in[9];
    const float* Whr_w = (const float*)d_in[10];
    const float* Whr_b = (const float*)d_in[11];
    const float* Whh_w = (const float*)d_in[12];
    const float* Whh_b = (const float*)d_in[13];
    const void*  lengths = d_in[14];

    cudaFuncSetAttribute(input_proj_kernel,
                         cudaFuncAttributeMaxDynamicSharedMemorySize, PA_SMEM);
    cudaFuncSetAttribute(gru_step_kernel,
                         cudaFuncAttributeMaxDynamicSharedMemorySize, PB_SMEM);

    init_misc_kernel<<<1, 128>>>();
    input_proj_kernel<<<256 * 24, 256, PA_SMEM>>>(input, Wiz_w, Wir_w, Wih_w);

    int write_last = (out_size >= TSTEPS * BATCH * NH + BATCH * NH) ? 1 : 0;
    gru_step_kernel<<<NBLK, 256, PB_SMEM>>>(
        h0, Whz_w, Whr_w, Whh_w, Whz_b, Whr_b, Whh_b,
        Wiz_b, Wir_b, Wih_b, lengths, (float*)d_out, write_last);
}